// round 2
// baseline (speedup 1.0000x reference)
#include <cuda_runtime.h>
#include <cuda_bf16.h>
#include <stdint.h>

#define NN 100000
#define NE 1600000
#define HID 128

// ---------------- device scratch (allocation-free rule: __device__ globals) ----
__device__ int   g_src[NE];
__device__ int   g_dst[NE];
__device__ float g_dis[NN];          // deg, then rsqrt(deg)
__device__ int   g_cursor[NN];       // count, then fill cursor
__device__ int   g_rowptr[NN + 1];
__device__ int   g_partials[256];
__device__ int   g_csrsrc[NE];
__device__ float g_csrcoef[NE];
__device__ float g_h1[(size_t)NN * HID];
__device__ float g_agg[(size_t)NN * HID];
__device__ int   g_flag64;

// ---------------- K0: detect edge_index dtype (int32 vs int64) ----------------
__global__ void k_detect(const void* ei) {
    const long long* p = (const long long*)ei;
    int lane = threadIdx.x;                       // 32 threads
    // sample within first NE int64 slots (safe under both interpretations)
    long long idx = (long long)lane * (NE / 32);
    long long v = p[idx];
    bool ok = (v >= 0 && v < NN);
    unsigned m = __ballot_sync(0xFFFFFFFFu, ok);
    if (lane == 0) g_flag64 = (m == 0xFFFFFFFFu) ? 1 : 0;
}

// ---------------- K1: normalize edge_index into int32 scratch -----------------
__global__ void k_convert(const void* ei) {
    int e = blockIdx.x * blockDim.x + threadIdx.x;
    if (e >= NE) return;
    if (g_flag64) {
        const long long* p = (const long long*)ei;
        g_src[e] = (int)p[e];
        g_dst[e] = (int)p[e + NE];
    } else {
        const int* p = (const int*)ei;
        g_src[e] = p[e];
        g_dst[e] = p[e + NE];
    }
}

// ---------------- K2: init deg=1 (self loop), count=0 -------------------------
__global__ void k_init(void) {
    int i = blockIdx.x * blockDim.x + threadIdx.x;
    if (i < NN) { g_dis[i] = 1.0f; g_cursor[i] = 0; }
}

// ---------------- K3: degree + in-degree histogram -----------------------------
__global__ void k_deg(const float* __restrict__ w) {
    int e = blockIdx.x * blockDim.x + threadIdx.x;
    if (e >= NE) return;
    int d = g_dst[e];
    atomicAdd(&g_dis[d], w[e]);
    atomicAdd(&g_cursor[d], 1);
}

// ---------------- K4: dis = rsqrt(deg) -----------------------------------------
__global__ void k_rsqrt(void) {
    int i = blockIdx.x * blockDim.x + threadIdx.x;
    if (i < NN) g_dis[i] = rsqrtf(g_dis[i]);
}

// ---------------- K5: exclusive scan of counts -> rowptr ------------------------
#define SCHUNK 512
#define NCHUNK ((NN + SCHUNK - 1) / SCHUNK)

__global__ void k_scan1(void) {        // <<<NCHUNK, 512>>>
    __shared__ int sh[SCHUNK];
    int t = threadIdx.x;
    int idx = blockIdx.x * SCHUNK + t;
    int v = (idx < NN) ? g_cursor[idx] : 0;
    sh[t] = v;
    __syncthreads();
    for (int off = 1; off < SCHUNK; off <<= 1) {
        int u = (t >= off) ? sh[t - off] : 0;
        __syncthreads();
        sh[t] += u;
        __syncthreads();
    }
    if (idx < NN) g_rowptr[idx] = sh[t] - v;      // exclusive, pre-offset
    if (t == SCHUNK - 1) g_partials[blockIdx.x] = sh[SCHUNK - 1];
}

__global__ void k_scan2(void) {        // <<<1,1>>>
    int acc = 0;
    for (int b = 0; b < NCHUNK; b++) {
        int v = g_partials[b];
        g_partials[b] = acc;
        acc += v;
    }
}

__global__ void k_scan3(void) {        // add chunk offsets; cursor = rowptr copy
    int i = blockIdx.x * blockDim.x + threadIdx.x;
    if (i < NN) {
        int r = g_rowptr[i] + g_partials[i >> 9];
        g_rowptr[i] = r;
        g_cursor[i] = r;
    }
    if (i == 0) g_rowptr[NN] = NE;
}

// ---------------- K6: fill CSR (src index + precomputed norm coef) -------------
__global__ void k_fill(const float* __restrict__ w) {
    int e = blockIdx.x * blockDim.x + threadIdx.x;
    if (e >= NE) return;
    int d = g_dst[e];
    int s = g_src[e];
    int pos = atomicAdd(&g_cursor[d], 1);
    g_csrsrc[pos]  = s;
    g_csrcoef[pos] = g_dis[s] * w[e] * g_dis[d];
}

// ---------------- K7: layer 1 (scalar aggregation + expand to 128) -------------
// a1[d] = sum_e coef*x[src] + dis[d]^2 * x[d];  h1[d][f] = relu(a1*W1[f]+b1[f])
__global__ void k_layer1(const float* __restrict__ x,
                         const float* __restrict__ W1,
                         const float* __restrict__ b1) {
    int gt   = blockIdx.x * blockDim.x + threadIdx.x;
    int node = gt >> 5;
    int lane = gt & 31;
    if (node >= NN) return;
    int s0 = g_rowptr[node], s1 = g_rowptr[node + 1];
    float p = 0.f;
    for (int j = s0 + lane; j < s1; j += 32)
        p = fmaf(g_csrcoef[j], x[g_csrsrc[j]], p);
    #pragma unroll
    for (int o = 16; o; o >>= 1) p += __shfl_xor_sync(0xFFFFFFFFu, p, o);
    float dd = g_dis[node];
    float a  = p + dd * dd * x[node];
    size_t base = (size_t)node * HID;
    #pragma unroll
    for (int k = 0; k < 4; k++) {
        int f = lane + 32 * k;
        g_h1[base + f] = fmaxf(fmaf(a, W1[f], b1[f]), 0.f);
    }
}

// ---------------- K8: layer-2 SpMM aggregation at width 128 --------------------
// agg[d][f] = dis[d]^2 * h1[d][f] + sum_j coef_j * h1[src_j][f]
__global__ void k_agg(void) {          // <<<NN, 128>>>
    int node = blockIdx.x;
    int f = threadIdx.x;
    float dd = g_dis[node];
    float acc = dd * dd * g_h1[(size_t)node * HID + f];
    int s0 = g_rowptr[node], s1 = g_rowptr[node + 1];
    for (int j = s0; j < s1; j++) {
        int   s = g_csrsrc[j];
        float c = g_csrcoef[j];
        acc = fmaf(c, g_h1[(size_t)s * HID + f], acc);
    }
    g_agg[(size_t)node * HID + f] = acc;
}

// ---------------- K9: fused MLP head -------------------------------------------
// h2 = relu(agg@W2 + b2) [256]; h3 = relu(h2@Wl1 + bl1) [128]; out = h3@Wl2 + bl2
#define NT 16
__global__ void k_mlp(const float* __restrict__ W2,  const float* __restrict__ b2,
                      const float* __restrict__ Wl1, const float* __restrict__ bl1,
                      const float* __restrict__ Wl2, const float* __restrict__ bl2,
                      float* __restrict__ out) {     // <<<ceil(N/NT), 256>>>
    __shared__ float vsh[NT][HID];
    __shared__ float h2sh[NT][2 * HID];
    __shared__ float h3sh[NT][HID];
    int base = blockIdx.x * NT;
    int t = threadIdx.x;

    // load agg tile
    for (int i = t; i < NT * HID; i += 256) {
        int n = i >> 7, f = i & 127;
        int node = base + n;
        vsh[n][f] = (node < NN) ? g_agg[(size_t)node * HID + f] : 0.f;
    }
    __syncthreads();

    // phase 1: c = t in [0,256)
    {
        float acc[NT];
        float bb = b2[t];
        #pragma unroll
        for (int n = 0; n < NT; n++) acc[n] = bb;
        #pragma unroll 4
        for (int f = 0; f < HID; f++) {
            float wf = W2[f * 256 + t];
            #pragma unroll
            for (int n = 0; n < NT; n++) acc[n] = fmaf(vsh[n][f], wf, acc[n]);
        }
        #pragma unroll
        for (int n = 0; n < NT; n++) h2sh[n][t] = fmaxf(acc[n], 0.f);
    }
    __syncthreads();

    // phase 2: g = t&127, node-half = t>>7
    {
        int g  = t & 127;
        int nb = (t >> 7) * (NT / 2);
        float acc[NT / 2];
        float bb = bl1[g];
        #pragma unroll
        for (int n = 0; n < NT / 2; n++) acc[n] = bb;
        #pragma unroll 4
        for (int c = 0; c < 2 * HID; c++) {
            float wl = Wl1[c * HID + g];
            #pragma unroll
            for (int n = 0; n < NT / 2; n++) acc[n] = fmaf(h2sh[nb + n][c], wl, acc[n]);
        }
        #pragma unroll
        for (int n = 0; n < NT / 2; n++) h3sh[nb + n][g] = fmaxf(acc[n], 0.f);
    }
    __syncthreads();

    // phase 3: output scalar per node
    if (t < NT) {
        int node = base + t;
        if (node < NN) {
            float s = bl2[0];
            #pragma unroll 4
            for (int g = 0; g < HID; g++) s = fmaf(h3sh[t][g], Wl2[g], s);
            out[node] = s;
        }
    }
}

// ---------------- launch ---------------------------------------------------------
extern "C" void kernel_launch(void* const* d_in, const int* in_sizes, int n_in,
                              void* d_out, int out_size) {
    const float* x   = (const float*)d_in[0];
    const void*  ei  = d_in[1];
    const float* w   = (const float*)d_in[2];
    const float* W1  = (const float*)d_in[3];
    const float* b1  = (const float*)d_in[4];
    const float* W2  = (const float*)d_in[5];
    const float* b2  = (const float*)d_in[6];
    const float* Wl1 = (const float*)d_in[7];
    const float* bl1 = (const float*)d_in[8];
    const float* Wl2 = (const float*)d_in[9];
    const float* bl2 = (const float*)d_in[10];
    float* out = (float*)d_out;

    const int TB = 256;
    const int EB = (NE + TB - 1) / TB;
    const int VB = (NN + TB - 1) / TB;

    k_detect<<<1, 32>>>(ei);
    k_convert<<<EB, TB>>>(ei);
    k_init<<<VB, TB>>>();
    k_deg<<<EB, TB>>>(w);
    k_rsqrt<<<VB, TB>>>();
    k_scan1<<<NCHUNK, SCHUNK>>>();
    k_scan2<<<1, 1>>>();
    k_scan3<<<VB, TB>>>();
    k_fill<<<EB, TB>>>(w);
    k_layer1<<<(NN * 32 + TB - 1) / TB, TB>>>(x, W1, b1);
    k_agg<<<NN, HID>>>();
    k_mlp<<<(NN + NT - 1) / NT, TB>>>(W2, b2, Wl1, bl1, Wl2, bl2, out);
}